// round 1
// baseline (speedup 1.0000x reference)
#include <cuda_runtime.h>

#define NB 128
#define NWARP 32
#define THREADS 1024
#define NITER 60

__global__ void __launch_bounds__(THREADS, 1)
gfusedmax_kernel(const float* __restrict__ x,
                 const float* __restrict__ A,
                 float* __restrict__ out)
{
    const int b    = blockIdx.x;
    const int tid  = threadIdx.x;
    const int lane = tid & 31;
    const int warp = tid >> 5;
    const int rbase = warp * 4;          // 4 rows per warp, 32 warps -> 128 rows

    __shared__ float sy[NB];             // step * y
    __shared__ float ys[NB];             // y
    __shared__ float xs[NB];             // x
    __shared__ float rs[NB];             // row sums
    __shared__ float colpart[NWARP][NB]; // per-warp column partials (16 KB)
    __shared__ float sorted_s[NB];
    __shared__ float csum[2][NB];
    __shared__ float wsum[4], wcnt[4];

    const float step = 1.0f / 256.0f;    // 1/(2N) exactly

    // ---- init: y = x, sy = step*x ----
    if (tid < NB) {
        float v = x[(size_t)b * NB + tid];
        xs[tid] = v;
        ys[tid] = v;
        sy[tid] = step * v;
    }

    // ---- load clip bounds into registers, z = 0 ----
    float w[4][4], z[4][4];
    const float* Ab = A + (size_t)b * NB * NB;
    #pragma unroll
    for (int r = 0; r < 4; ++r) {
        #pragma unroll
        for (int c = 0; c < 4; ++c) {
            w[r][c] = Ab[(rbase + r) * NB + lane + 32 * c];  // fully coalesced
            z[r][c] = 0.0f;
        }
    }
    __syncthreads();

    // ---- 60 projected-gradient iterations ----
    #pragma unroll 1
    for (int it = 0; it < NITER; ++it) {
        float syc[4], syr[4];
        #pragma unroll
        for (int c = 0; c < 4; ++c) syc[c] = sy[lane + 32 * c];   // conflict-free
        #pragma unroll
        for (int r = 0; r < 4; ++r) syr[r] = sy[rbase + r];       // broadcast

        float rowacc[4] = {0.f, 0.f, 0.f, 0.f};
        float colacc[4] = {0.f, 0.f, 0.f, 0.f};

        #pragma unroll
        for (int r = 0; r < 4; ++r) {
            #pragma unroll
            for (int c = 0; c < 4; ++c) {
                float v  = z[r][c] + (syr[r] - syc[c]);
                float ww = w[r][c];
                v = fminf(fmaxf(v, -ww), ww);
                z[r][c] = v;
                rowacc[r] += v;
                colacc[c] += v;
            }
        }

        // column partials: lane l owns cols {l, l+32, l+64, l+96} of this warp's rows
        #pragma unroll
        for (int c = 0; c < 4; ++c)
            colpart[warp][lane + 32 * c] = colacc[c];

        // row sums: butterfly reduce across the warp (deterministic)
        #pragma unroll
        for (int r = 0; r < 4; ++r) {
            #pragma unroll
            for (int s = 16; s > 0; s >>= 1)
                rowacc[r] += __shfl_xor_sync(0xffffffffu, rowacc[r], s);
        }
        if (lane < 4) rs[rbase + lane] = rowacc[lane];

        __syncthreads();

        if (tid < NB) {
            float cs = 0.0f;
            #pragma unroll
            for (int ww2 = 0; ww2 < NWARP; ++ww2)
                cs += colpart[ww2][tid];            // conflict-free columns
            float y = xs[tid] - rs[tid] + cs;
            ys[tid] = y;
            sy[tid] = step * y;
        }
        __syncthreads();
    }

    // ---- sparsemax over ys[0..127] ----
    // rank sort (O(N^2), branch-free, deterministic tie-break by index)
    if (tid < NB) {
        float v = ys[tid];
        int rank = 0;
        #pragma unroll
        for (int j = 0; j < NB; ++j) {
            float u = ys[j];
            rank += (u > v) || (u == v && j < tid);
        }
        sorted_s[rank] = v;                          // descending
    }
    __syncthreads();

    // inclusive scan (Hillis-Steele, ping-pong)
    if (tid < NB) csum[0][tid] = sorted_s[tid];
    __syncthreads();
    int src = 0;
    for (int off = 1; off < NB; off <<= 1) {
        if (tid < NB) {
            float v = csum[src][tid];
            if (tid >= off) v += csum[src][tid - off];
            csum[1 - src][tid] = v;
        }
        __syncthreads();
        src = 1 - src;
    }

    // mask + deterministic reduction of (sum, count)
    if (tid < NB) {
        float s  = sorted_s[tid];
        float cu = csum[src][tid];
        float k  = (float)(tid + 1);
        bool  m  = (1.0f + k * s > cu);
        float sv = m ? s : 0.0f;
        float sc = m ? 1.0f : 0.0f;
        #pragma unroll
        for (int sft = 16; sft > 0; sft >>= 1) {
            sv += __shfl_xor_sync(0xffffffffu, sv, sft);
            sc += __shfl_xor_sync(0xffffffffu, sc, sft);
        }
        if (lane == 0) { wsum[warp] = sv; wcnt[warp] = sc; }
    }
    __syncthreads();

    if (tid < NB) {
        float ssum = ((wsum[0] + wsum[1]) + (wsum[2] + wsum[3]));
        float scnt = ((wcnt[0] + wcnt[1]) + (wcnt[2] + wcnt[3]));
        float tau  = (ssum - 1.0f) / scnt;
        out[(size_t)b * NB + tid] = fmaxf(ys[tid] - tau, 0.0f);
    }
}

extern "C" void kernel_launch(void* const* d_in, const int* in_sizes, int n_in,
                              void* d_out, int out_size)
{
    const float* x = (const float*)d_in[0];   // [B, 128]
    const float* A = (const float*)d_in[1];   // [B, 128, 128]
    float* out = (float*)d_out;               // [B, 128] float32

    int B = in_sizes[0] / NB;                 // 4096
    gfusedmax_kernel<<<B, THREADS>>>(x, A, out);
}